// round 5
// baseline (speedup 1.0000x reference)
#include <cuda_runtime.h>
#include <cuda_bf16.h>

#define T_LEN 4096
#define HID 10
#define NG 40          // 4*HID
#define EMB 256
#define OUT 50257

#define NBLK 147       // 1 LSTM block + 146 workers (all co-resident on 148 SMs)
#define NWRK 146
#define XG_TILES 128   // 32 timesteps per tile
#define OTILE 1024
#define TTILE 128
#define NOT  ((OUT + OTILE - 1) / OTILE)     // 50 output tiles
#define NITEM (NOT * (T_LEN / TTILE))        // 1600 work items

// Scratch (__device__ globals; no allocation allowed). g_xg padded for the
// harmless deep-prefetch overrun (4 steps ahead, never consumed).
__device__ float g_xg[(T_LEN + 8) * NG];
__device__ float g_hs[T_LEN * HID];
__device__ int   g_xg_done;   // workers -> LSTM: xg tiles completed
__device__ int   g_progress;  // LSTM -> workers: timesteps published

// ---------------------------------------------------------------------------
// fast approx helpers (same MUFU class as the passing __expf/__fdividef build)
// ---------------------------------------------------------------------------
__device__ __forceinline__ float ex2a(float x) {
    float r; asm("ex2.approx.ftz.f32 %0, %1;" : "=f"(r) : "f"(x)); return r;
}
__device__ __forceinline__ float rcpa(float x) {
    float r; asm("rcp.approx.ftz.f32 %0, %1;" : "=f"(r) : "f"(x)); return r;
}
__device__ __forceinline__ int ld_acq(const int* p) {
    int v; asm volatile("ld.acquire.gpu.s32 %0, [%1];" : "=r"(v) : "l"(p) : "memory"); return v;
}
__device__ __forceinline__ void st_rel(int* p, int v) {
    asm volatile("st.release.gpu.s32 [%0], %1;" :: "l"(p), "r"(v) : "memory");
}

// ---------------------------------------------------------------------------
// init: reset counters every launch (graph replays must be deterministic)
// ---------------------------------------------------------------------------
__global__ void init_kernel() {
    g_xg_done = 0;
    g_progress = 0;
}

// ---------------------------------------------------------------------------
// Fused persistent kernel.
//   block 0           : warp 0 runs the sequential LSTM (waits for xg).
//   blocks 1..128     : compute one xg tile (32 t's) each, then join out pool.
//   blocks 1..146     : persistent output-GEMM workers, gated on g_progress.
// ---------------------------------------------------------------------------
__global__ void __launch_bounds__(256, 1)
fused_kernel(const int* __restrict__ x,
             const float* __restrict__ emb,
             const float* __restrict__ w_ih,
             const float* __restrict__ w_hh,
             const float* __restrict__ b_ih,
             const float* __restrict__ b_hh,
             const float* __restrict__ W,
             const float* __restrict__ bo,
             float* __restrict__ out) {
    const int bid = blockIdx.x;
    const int tid = threadIdx.x;
    const int lane = tid & 31;
    const int w    = tid >> 5;

    __shared__ float smem[32 * 65 * 4];   // 8320 floats: xg stage (32 rows, pad-260) / hs tile
    __shared__ int   srow[32];

    // =====================================================================
    // LSTM block
    // =====================================================================
    if (bid == 0) {
        if (tid >= 32) return;
        const int k  = lane;
        const int kb = k & 7;
        const unsigned M = 0xffffffffu;

        float whA[HID], whB[HID];
        #pragma unroll
        for (int j = 0; j < HID; ++j) {
            whA[j] = w_hh[k * HID + j];
            whB[j] = w_hh[(32 + kb) * HID + j];
        }

        const float L2E = 1.4426950408889634f;
        const bool isTanh = (k >= 20 && k < 30);
        const float ec2 = isTanh ? (-2.0f * L2E) : (-L2E);  // exponent scale
        const float s1f = isTanh ?  2.0f : 1.0f;            // a = s1*rcp(1+p)+s0
        const float s0f = isTanh ? -1.0f : 0.0f;

        // wait for all xg tiles
        if (k == 0) {
            while (ld_acq(&g_xg_done) < XG_TILES) __nanosleep(60);
        }
        __syncwarp();

        float hv[HID];
        #pragma unroll
        for (int j = 0; j < HID; ++j) hv[j] = 0.f;
        float c = 0.f;

        // 4-deep prefetch ring (fully unrolled -> static register indices)
        float xaP[4], xbP[4];
        #pragma unroll
        for (int p = 0; p < 4; ++p) {
            xaP[p] = g_xg[p * NG + k];
            xbP[p] = g_xg[p * NG + 32 + kb];
        }

        for (int t = 0; t < T_LEN; t += 4) {
            #pragma unroll
            for (int u = 0; u < 4; ++u) {
                const int tt = t + u;
                float zA = xaP[u], zB = xbP[u];
                // refill slot u with step tt+4 (arrives ~600+ cyc before use)
                xaP[u] = g_xg[(tt + 4) * NG + k];
                xbP[u] = g_xg[(tt + 4) * NG + 32 + kb];

                // z = xg + w_hh . h   (two chains of 5 to halve chain latency)
                float zA2 = whA[5] * hv[5];
                float zB2 = whB[5] * hv[5];
                #pragma unroll
                for (int j = 0; j < 5; ++j) {
                    zA  = fmaf(whA[j], hv[j], zA);
                    zB  = fmaf(whB[j], hv[j], zB);
                }
                #pragma unroll
                for (int j = 6; j < HID; ++j) {
                    zA2 = fmaf(whA[j], hv[j], zA2);
                    zB2 = fmaf(whB[j], hv[j], zB2);
                }
                zA += zA2; zB += zB2;

                // activation: sigmoid = rcp(1+2^(-z*log2e)); tanh = 2*rcp(1+2^(-2z*log2e))-1
                float pA = ex2a(ec2 * zA);
                float aA = fmaf(s1f, rcpa(1.0f + pA), s0f);
                float pB = ex2a(-L2E * zB);
                float aB = rcpa(1.0f + pB);

                // redistribute to unit lanes (same verified mapping)
                float fv = __shfl_sync(M, aA, (k + 10) & 31);
                float gv = __shfl_sync(M, aA, (k + 20) & 31);
                float o1 = __shfl_sync(M, aA, (k + 30) & 31);
                float o2 = __shfl_sync(M, aB, (k + 30) & 31);
                float ov = (k < 2) ? o1 : o2;

                c = fmaf(fv, c, aA * gv);
                float pc = ex2a(-2.0f * L2E * c);
                float h  = ov * fmaf(2.0f, rcpa(1.0f + pc), -1.0f);

                if (k < HID) g_hs[tt * HID + k] = h;

                #pragma unroll
                for (int j = 0; j < HID; ++j) hv[j] = __shfl_sync(M, h, j);
            }
            if (((t + 4) & 127) == 0) {      // publish every 128 steps
                __syncwarp();
                __threadfence();
                if (k == 0) st_rel(&g_progress, t + 4);
            }
        }
        return;
    }

    // =====================================================================
    // Worker blocks: phase 1 — xg tile (blocks 1..128)
    // xg[t][g] = emb[x[t]] . w_ih[g] + b_ih[g] + b_hh[g]
    // =====================================================================
    const int wb = bid - 1;                  // 0..145
    if (wb < XG_TILES) {
        const int t0 = wb * 32;
        if (tid < 32) srow[tid] = x[t0 + tid];
        __syncthreads();

        // stage 32 emb rows into smem, pad to 260 floats/row (conflict-free LDS.128)
        float4* sm4 = reinterpret_cast<float4*>(smem);
        for (int idx = tid; idx < 32 * 64; idx += 256) {
            const int r = idx >> 6, q = idx & 63;
            sm4[r * 65 + q] =
                reinterpret_cast<const float4*>(emb)[(size_t)srow[r] * 64 + q];
        }
        __syncthreads();

        // lane = t, warp covers gates w + 8r
        const float4* er4 = sm4 + lane * 65;
        float acc[5];
        #pragma unroll
        for (int r = 0; r < 5; ++r) acc[r] = 0.f;

        for (int cc = 0; cc < 64; cc += 4) {
            float4 e0 = er4[cc], e1 = er4[cc + 1], e2 = er4[cc + 2], e3 = er4[cc + 3];
            #pragma unroll
            for (int r = 0; r < 5; ++r) {
                const float4* w4 =
                    reinterpret_cast<const float4*>(w_ih + (w + r * 8) * EMB) + cc;
                float4 w0 = __ldg(w4), w1 = __ldg(w4 + 1),
                       w2 = __ldg(w4 + 2), w3 = __ldg(w4 + 3);
                float s = acc[r];
                s = fmaf(e0.x, w0.x, s); s = fmaf(e0.y, w0.y, s);
                s = fmaf(e0.z, w0.z, s); s = fmaf(e0.w, w0.w, s);
                s = fmaf(e1.x, w1.x, s); s = fmaf(e1.y, w1.y, s);
                s = fmaf(e1.z, w1.z, s); s = fmaf(e1.w, w1.w, s);
                s = fmaf(e2.x, w2.x, s); s = fmaf(e2.y, w2.y, s);
                s = fmaf(e2.z, w2.z, s); s = fmaf(e2.w, w2.w, s);
                s = fmaf(e3.x, w3.x, s); s = fmaf(e3.y, w3.y, s);
                s = fmaf(e3.z, w3.z, s); s = fmaf(e3.w, w3.w, s);
                acc[r] = s;
            }
        }
        const int t = t0 + lane;
        #pragma unroll
        for (int r = 0; r < 5; ++r) {
            const int g = w + r * 8;
            g_xg[t * NG + g] = acc[r] + b_ih[g] + b_hh[g];
        }
        __syncthreads();
        if (tid == 0) {
            __threadfence();
            atomicAdd(&g_xg_done, 1);
        }
    }

    // =====================================================================
    // Worker blocks: phase 2 — output GEMM, gated on LSTM progress
    // logits[t][o] = hs[t] . W[o] + bo[o]
    // =====================================================================
    for (int i = wb; i < NITEM; i += NWRK) {
        const int tile_t = i / NOT;
        const int tile_o = i - tile_t * NOT;
        const int t0 = tile_t * TTILE;
        const int need = t0 + TTILE;

        if (tid == 0) {
            while (ld_acq(&g_progress) < need) __nanosleep(200);
        }
        __syncthreads();   // also protects smem reuse across items

        // stage hs tile
        for (int s = tid; s < TTILE * HID; s += 256)
            smem[s] = g_hs[t0 * HID + s];
        __syncthreads();

        const int o0 = tile_o * OTILE + w * 128 + lane;
        float wr[4][HID], br[4];
        bool  valid[4];
        #pragma unroll
        for (int r = 0; r < 4; ++r) {
            const int o = o0 + 32 * r;
            valid[r] = (o < OUT);
            br[r] = valid[r] ? bo[o] : 0.f;
            #pragma unroll
            for (int kk = 0; kk < HID; ++kk)
                wr[r][kk] = valid[r] ? W[o * HID + kk] : 0.f;
        }

        for (int ts = 0; ts < TTILE; ++ts) {
            float h[HID];
            #pragma unroll
            for (int kk = 0; kk < HID; ++kk) h[kk] = smem[ts * HID + kk];

            const size_t row = (size_t)(t0 + ts) * OUT;
            #pragma unroll
            for (int r = 0; r < 4; ++r) {
                float acc = br[r];
                #pragma unroll
                for (int kk = 0; kk < HID; ++kk)
                    acc = fmaf(h[kk], wr[r][kk], acc);
                if (valid[r]) out[row + o0 + 32 * r] = acc;
            }
        }
    }
}

// ---------------------------------------------------------------------------
extern "C" void kernel_launch(void* const* d_in, const int* in_sizes, int n_in,
                              void* d_out, int out_size) {
    const int*   x     = (const int*)  d_in[0];
    const float* emb   = (const float*)d_in[1];
    const float* w_ih  = (const float*)d_in[2];
    const float* w_hh  = (const float*)d_in[3];
    const float* b_ih  = (const float*)d_in[4];
    const float* b_hh  = (const float*)d_in[5];
    const float* W_out = (const float*)d_in[6];
    const float* b_out = (const float*)d_in[7];
    float* out = (float*)d_out;

    init_kernel<<<1, 1>>>();
    fused_kernel<<<NBLK, 256>>>(x, emb, w_ih, w_hh, b_ih, b_hh, W_out, b_out, out);
}